// round 2
// baseline (speedup 1.0000x reference)
#include <cuda_runtime.h>
#include <cuda_bf16.h>

#define NUM_B 16384
#define NUM_K 50
#define H_DIM 64
#define REG_C 0.01

// scratch: per-block partials [err_sq_sum, ie_norm_sum, ue_norm]
__device__ double g_partial[NUM_B * 3];

__global__ void __launch_bounds__(256) mf_main_kernel(
    const float* __restrict__ user_weight,
    const float* __restrict__ item_weight,
    const float* __restrict__ user_bias,
    const float* __restrict__ item_bias,
    const float* __restrict__ bias,
    const float* __restrict__ target,
    const int*   __restrict__ user,
    const int*   __restrict__ item,
    float*       __restrict__ out)
{
    const int b    = blockIdx.x;
    const int tid  = threadIdx.x;
    const int wid  = tid >> 5;
    const int lane = tid & 31;

    __shared__ float  s_ue[H_DIM];
    __shared__ double s_err[8];
    __shared__ double s_ien[8];

    const int u = user[b];
    if (tid < 32) {
        const float ubias = user_bias[u];
        float2 w = reinterpret_cast<const float2*>(user_weight + (size_t)u * H_DIM)[tid];
        s_ue[2 * tid]     = w.x + ubias;
        s_ue[2 * tid + 1] = w.y + ubias;
    }
    __syncthreads();

    const float ue0 = s_ue[2 * lane];
    const float ue1 = s_ue[2 * lane + 1];
    const float bias0 = bias[0];

    double err_acc = 0.0;
    double ien_acc = 0.0;

    for (int k = wid; k < NUM_K; k += 8) {
        const int it = item[b * NUM_K + k];
        const float ibias = item_bias[it];
        float2 w = reinterpret_cast<const float2*>(item_weight + (size_t)it * H_DIM)[lane];
        const float ie0 = w.x + ibias;
        const float ie1 = w.y + ibias;
        float dot = ie0 * ue0 + ie1 * ue1;
        float sq  = ie0 * ie0 + ie1 * ie1;
        #pragma unroll
        for (int off = 16; off > 0; off >>= 1) {
            dot += __shfl_xor_sync(0xFFFFFFFFu, dot, off);
            sq  += __shfl_xor_sync(0xFFFFFFFFu, sq,  off);
        }
        if (lane == 0) {
            const float pred = dot + bias0;
            out[b * NUM_K + k] = pred;
            const float e = pred - target[b * NUM_K + k];
            err_acc += (double)(e * e);
            ien_acc += (double)sqrtf(sq);
        }
    }

    if (lane == 0) {
        s_err[wid] = err_acc;
        s_ien[wid] = ien_acc;
    }
    __syncthreads();

    if (tid == 0) {
        double e = 0.0, n = 0.0;
        #pragma unroll
        for (int w = 0; w < 8; w++) { e += s_err[w]; n += s_ien[w]; }
        float uesq = 0.0f;
        #pragma unroll
        for (int h = 0; h < H_DIM; h++) uesq += s_ue[h] * s_ue[h];
        g_partial[3 * b]     = e;
        g_partial[3 * b + 1] = n;
        g_partial[3 * b + 2] = (double)sqrtf(uesq);
    }
}

__global__ void __launch_bounds__(256) mf_finalize_kernel(float* __restrict__ out)
{
    __shared__ double se[256], sn[256], su[256];
    const int tid = threadIdx.x;
    double e = 0.0, n = 0.0, u = 0.0;
    for (int i = tid; i < NUM_B; i += 256) {
        e += g_partial[3 * i];
        n += g_partial[3 * i + 1];
        u += g_partial[3 * i + 2];
    }
    se[tid] = e; sn[tid] = n; su[tid] = u;
    __syncthreads();
    for (int s = 128; s > 0; s >>= 1) {
        if (tid < s) {
            se[tid] += se[tid + s];
            sn[tid] += sn[tid + s];
            su[tid] += su[tid + s];
        }
        __syncthreads();
    }
    if (tid == 0) {
        const double total = (double)NUM_B * (double)NUM_K;
        double mse = se[0] / total;
        double reg = REG_C * (su[0] / (double)NUM_B) + REG_C * (sn[0] / total);
        out[NUM_B * NUM_K] = (float)(mse + reg);
    }
}

extern "C" void kernel_launch(void* const* d_in, const int* in_sizes, int n_in,
                              void* d_out, int out_size)
{
    const float* user_weight = (const float*)d_in[0];
    const float* item_weight = (const float*)d_in[1];
    const float* user_bias   = (const float*)d_in[2];
    const float* item_bias   = (const float*)d_in[3];
    const float* bias        = (const float*)d_in[4];
    const float* target      = (const float*)d_in[5];
    const int*   user        = (const int*)d_in[6];
    const int*   item        = (const int*)d_in[7];
    float*       out         = (float*)d_out;

    mf_main_kernel<<<NUM_B, 256>>>(user_weight, item_weight, user_bias, item_bias,
                                   bias, target, user, item, out);
    mf_finalize_kernel<<<1, 256>>>(out);
}

// round 3
// speedup vs baseline: 1.0929x; 1.0929x over previous
#include <cuda_runtime.h>
#include <cuda_bf16.h>

#define NUM_B 16384
#define NUM_K 50
#define H_DIM 64
#define REG_C 0.01
#define MAXI 7          // max items per warp (8 warps, 50 items)

// SoA per-block partials + stage-1 scratch
__device__ double g_err[NUM_B];
__device__ double g_ien[NUM_B];
__device__ double g_uen[NUM_B];
__device__ double g_s1[64 * 3];

__global__ void __launch_bounds__(256) mf_main_kernel(
    const float* __restrict__ user_weight,
    const float* __restrict__ item_weight,
    const float* __restrict__ user_bias,
    const float* __restrict__ item_bias,
    const float* __restrict__ bias,
    const float* __restrict__ target,
    const int*   __restrict__ user,
    const int*   __restrict__ item,
    float*       __restrict__ out)
{
    const int b    = blockIdx.x;
    const int tid  = threadIdx.x;
    const int wid  = tid >> 5;
    const int lane = tid & 31;

    __shared__ float  s_ue[H_DIM];
    __shared__ double s_err[8];
    __shared__ double s_ien[8];

    // warp 0: stage user embedding into smem
    if (tid < 32) {
        const int u = user[b];
        const float ubias = user_bias[u];
        float2 w = reinterpret_cast<const float2*>(user_weight + (size_t)u * H_DIM)[tid];
        s_ue[2 * tid]     = w.x + ubias;
        s_ue[2 * tid + 1] = w.y + ubias;
    }

    // items per warp: warps 0,1 -> 7, warps 2..7 -> 6
    const int cnt = (57 - wid) >> 3;

    // --- pipelined prefetch: indices, then biases, then rows (7 independent LDG.64) ---
    int its[MAXI];
    #pragma unroll
    for (int i = 0; i < MAXI; i++) {
        if (i < cnt) its[i] = item[b * NUM_K + wid + 8 * i];
    }
    float ib[MAXI];
    #pragma unroll
    for (int i = 0; i < MAXI; i++) {
        if (i < cnt) ib[i] = item_bias[its[i]];
    }
    float2 r[MAXI];
    #pragma unroll
    for (int i = 0; i < MAXI; i++) {
        if (i < cnt) r[i] = reinterpret_cast<const float2*>(item_weight + (size_t)its[i] * H_DIM)[lane];
    }
    float tg[MAXI];
    #pragma unroll
    for (int i = 0; i < MAXI; i++) {
        if (i < cnt) tg[i] = target[b * NUM_K + wid + 8 * i];
    }
    const float bias0 = bias[0];

    __syncthreads();
    const float ue0 = s_ue[2 * lane];
    const float ue1 = s_ue[2 * lane + 1];

    float dot[MAXI], sq[MAXI];
    #pragma unroll
    for (int i = 0; i < MAXI; i++) {
        const float ie0 = r[i].x + ib[i];
        const float ie1 = r[i].y + ib[i];
        dot[i] = fmaf(ie0, ue0, ie1 * ue1);
        sq[i]  = fmaf(ie0, ie0, ie1 * ie1);
    }
    // interleaved shfl reductions (14 independent chains per round)
    #pragma unroll
    for (int off = 16; off > 0; off >>= 1) {
        #pragma unroll
        for (int i = 0; i < MAXI; i++) {
            dot[i] += __shfl_xor_sync(0xFFFFFFFFu, dot[i], off);
            sq[i]  += __shfl_xor_sync(0xFFFFFFFFu, sq[i],  off);
        }
    }

    double err_acc = 0.0, ien_acc = 0.0;
    if (lane == 0) {
        #pragma unroll
        for (int i = 0; i < MAXI; i++) {
            if (i < cnt) {
                const float pred = dot[i] + bias0;
                out[b * NUM_K + wid + 8 * i] = pred;
                const float e = pred - tg[i];
                err_acc += (double)(e * e);
                ien_acc += (double)sqrtf(sq[i]);
            }
        }
        s_err[wid] = err_acc;
        s_ien[wid] = ien_acc;
    }
    __syncthreads();

    if (tid == 0) {
        double e = 0.0, n = 0.0;
        #pragma unroll
        for (int w = 0; w < 8; w++) { e += s_err[w]; n += s_ien[w]; }
        float uesq = 0.0f;
        #pragma unroll
        for (int h = 0; h < H_DIM; h++) uesq += s_ue[h] * s_ue[h];
        g_err[b] = e;
        g_ien[b] = n;
        g_uen[b] = (double)sqrtf(uesq);
    }
}

__device__ __forceinline__ double warp_red(double v) {
    #pragma unroll
    for (int off = 16; off > 0; off >>= 1)
        v += __shfl_xor_sync(0xFFFFFFFFu, v, off);
    return v;
}

// stage 1: 64 CTAs x 256 threads, coalesced
__global__ void __launch_bounds__(256) mf_reduce1_kernel()
{
    __shared__ double se[8], sn[8], su[8];
    const int tid  = threadIdx.x;
    const int wid  = tid >> 5;
    const int lane = tid & 31;
    const int idx  = blockIdx.x * 256 + tid;

    double e = warp_red(g_err[idx]);
    double n = warp_red(g_ien[idx]);
    double u = warp_red(g_uen[idx]);
    if (lane == 0) { se[wid] = e; sn[wid] = n; su[wid] = u; }
    __syncthreads();
    if (tid == 0) {
        double te = 0.0, tn = 0.0, tu = 0.0;
        #pragma unroll
        for (int w = 0; w < 8; w++) { te += se[w]; tn += sn[w]; tu += su[w]; }
        g_s1[blockIdx.x * 3]     = te;
        g_s1[blockIdx.x * 3 + 1] = tn;
        g_s1[blockIdx.x * 3 + 2] = tu;
    }
}

// stage 2: 1 warp reduces 64 stage-1 partials and writes the scalar loss
__global__ void __launch_bounds__(32) mf_reduce2_kernel(float* __restrict__ out)
{
    const int lane = threadIdx.x;
    double e = g_s1[3 * lane]     + g_s1[3 * (lane + 32)];
    double n = g_s1[3 * lane + 1] + g_s1[3 * (lane + 32) + 1];
    double u = g_s1[3 * lane + 2] + g_s1[3 * (lane + 32) + 2];
    e = warp_red(e); n = warp_red(n); u = warp_red(u);
    if (lane == 0) {
        const double total = (double)NUM_B * (double)NUM_K;
        double mse = e / total;
        double reg = REG_C * (u / (double)NUM_B) + REG_C * (n / total);
        out[NUM_B * NUM_K] = (float)(mse + reg);
    }
}

extern "C" void kernel_launch(void* const* d_in, const int* in_sizes, int n_in,
                              void* d_out, int out_size)
{
    const float* user_weight = (const float*)d_in[0];
    const float* item_weight = (const float*)d_in[1];
    const float* user_bias   = (const float*)d_in[2];
    const float* item_bias   = (const float*)d_in[3];
    const float* bias        = (const float*)d_in[4];
    const float* target      = (const float*)d_in[5];
    const int*   user        = (const int*)d_in[6];
    const int*   item        = (const int*)d_in[7];
    float*       out         = (float*)d_out;

    mf_main_kernel<<<NUM_B, 256>>>(user_weight, item_weight, user_bias, item_bias,
                                   bias, target, user, item, out);
    mf_reduce1_kernel<<<64, 256>>>();
    mf_reduce2_kernel<<<1, 32>>>(out);
}